// round 14
// baseline (speedup 1.0000x reference)
#include <cuda_runtime.h>
#include <cuda_fp16.h>
#include <cstdint>

// ---------------- problem constants ----------------
#define TOKENS 8192
#define KDIM   4096
#define NDIM   11008

#define BM 128
#define BN 128
#define KT 64                  // k-tiles per output tile (64 halves each)
#define MT (TOKENS/BM)         // 64
#define NT (NDIM/BN)           // 86
#define TOTAL_TILES (MT*NT)    // 5504
#define GM 16                  // m-group for L2 reuse
#define STAGES 3
#define A_STG (BM*64*2)        // 16384 B
#define B_STG (BN*64*2)        // 16384 B
#define SMB   (STAGES*A_STG)
#define SM_DATA (STAGES*(A_STG+B_STG))      // 98304 B
#define SM_MBAR SM_DATA
#define SMEM_TOTAL (SM_DATA + 64)

__device__ __half g_X[(size_t)TOKENS * KDIM];
__device__ __half g_W[(size_t)NDIM   * KDIM];

// ---------------- helpers ----------------
__device__ __forceinline__ uint32_t smem_u32(const void* p) {
    uint32_t a;
    asm("{ .reg .u64 t; cvta.to.shared.u64 t, %1; cvt.u32.u64 %0, t; }" : "=r"(a) : "l"(p));
    return a;
}
__device__ __forceinline__ void cp16(uint32_t dst, const void* src) {
    asm volatile("cp.async.cg.shared.global [%0], [%1], 16;" :: "r"(dst), "l"(src));
}
__device__ __forceinline__ void cp_arrive_noinc(uint32_t mbar) {
    asm volatile("cp.async.mbarrier.arrive.noinc.shared::cta.b64 [%0];" :: "r"(mbar) : "memory");
}
__device__ __forceinline__ void mbar_init(uint32_t mbar, uint32_t cnt) {
    asm volatile("mbarrier.init.shared.b64 [%0], %1;" :: "r"(mbar), "r"(cnt) : "memory");
}
__device__ __forceinline__ void mbar_arrive(uint32_t mbar) {
    asm volatile("mbarrier.arrive.shared.b64 _, [%0];" :: "r"(mbar) : "memory");
}
__device__ __forceinline__ void wait_parity(uint32_t mbar, uint32_t ph) {
    asm volatile(
        "{\n\t.reg .pred P;\n\t"
        "LAB1_%=:\n\t"
        "mbarrier.try_wait.parity.acquire.cta.shared::cta.b64 P, [%0], %1, 0x989680;\n\t"
        "@P bra.uni LAB2_%=;\n\t"
        "bra.uni LAB1_%=;\n\t"
        "LAB2_%=:\n\t}"
        :: "r"(mbar), "r"(ph) : "memory");
}
__device__ __forceinline__ void ldmx4(uint32_t* r, uint32_t addr) {
    asm volatile("ldmatrix.sync.aligned.m8n8.x4.shared.b16 {%0,%1,%2,%3}, [%4];"
                 : "=r"(r[0]), "=r"(r[1]), "=r"(r[2]), "=r"(r[3]) : "r"(addr));
}
__device__ __forceinline__ void mma16816(float* c, const uint32_t* a, uint32_t b0, uint32_t b1) {
    asm volatile(
        "mma.sync.aligned.m16n8k16.row.col.f32.f16.f16.f32 "
        "{%0,%1,%2,%3}, {%4,%5,%6,%7}, {%8,%9}, {%0,%1,%2,%3};"
        : "+f"(c[0]), "+f"(c[1]), "+f"(c[2]), "+f"(c[3])
        : "r"(a[0]), "r"(a[1]), "r"(a[2]), "r"(a[3]), "r"(b0), "r"(b1));
}
__device__ __forceinline__ uint32_t pack_h2(float a, float b) {
    __half2 h = __floats2half2_rn(a, b);
    return *reinterpret_cast<uint32_t*>(&h);
}
__device__ __forceinline__ void tile_mn(int id, int& mt, int& nt) {
    int grp = id / (GM * NT);
    int rem = id - grp * (GM * NT);
    mt = grp * GM + (rem & (GM - 1));
    nt = rem / GM;
}

// ---------------- prep kernels: 2 vectors per thread ----------------
__global__ void __launch_bounds__(256) k_convert_x(const float4* __restrict__ x) {
    int i = (blockIdx.x * 256 + threadIdx.x) * 2;
    if (i >= TOKENS * KDIM / 4) return;
    float4 v0 = x[i], v1 = x[i + 1];
    ((uint2*)g_X)[i]     = make_uint2(pack_h2(v0.x, v0.y), pack_h2(v0.z, v0.w));
    ((uint2*)g_X)[i + 1] = make_uint2(pack_h2(v1.x, v1.y), pack_h2(v1.z, v1.w));
}
__global__ void __launch_bounds__(256) k_dequant_w(const int4* __restrict__ qw,
                                                   const float* __restrict__ scale) {
    int i = (blockIdx.x * 256 + threadIdx.x) * 2;
    if (i >= NDIM * KDIM / 4) return;
    int4 q0 = qw[i], q1 = qw[i + 1];
    float s = scale[i >> 10];
    ((uint2*)g_W)[i]     = make_uint2(pack_h2((float)(q0.x - 8) * s, (float)(q0.y - 8) * s),
                                      pack_h2((float)(q0.z - 8) * s, (float)(q0.w - 8) * s));
    ((uint2*)g_W)[i + 1] = make_uint2(pack_h2((float)(q1.x - 8) * s, (float)(q1.y - 8) * s),
                                      pack_h2((float)(q1.z - 8) * s, (float)(q1.w - 8) * s));
}

__global__ void k_nop() {}

// ---------------- persistent GEMM: continuous stage ring across tiles ----------------
__global__ void __launch_bounds__(256, 2) k_gemm(const float* __restrict__ bias,
                                                 float* __restrict__ out) {
    extern __shared__ char smem[];
    const uint32_t sb = smem_u32(smem);
    const int tid = threadIdx.x;
    const int wid = tid >> 5, lane = tid & 31;

    const uint32_t fullb  = sb + SM_MBAR;        // full[s]  (count 256)
    const uint32_t emptyb = sb + SM_MBAR + 24;   // empty[s] (count 8)

    // ---- loader constants (shared row offsets for A and B tiles) ----
    const int lrow = tid >> 3;
    const int lcol = (tid & 7) * 16;
    uint32_t soff[4], roff[4];
#pragma unroll
    for (int p = 0; p < 4; p++) {
        int row = lrow + p * 32;
        soff[p] = (uint32_t)(row * 128 + (lcol ^ ((row & 7) * 16)));
        roff[p] = (uint32_t)(row * (KDIM * 2) + lcol);
    }

    // ---- ldmatrix per-lane addressing (XOR form) ----
    const int wm = wid & 3, wn = wid >> 2;
    const int lm   = ((lane >> 3) & 1) * 8 + (lane & 7);
    const uint32_t colb = (lane >> 4) * 16;
    uint32_t o_a[2];
#pragma unroll
    for (int mi = 0; mi < 2; mi++) {
        int r = wm * 32 + mi * 16 + lm;
        o_a[mi] = (uint32_t)(r * 128) + (colb ^ ((r & 7) * 16));
    }
    uint32_t o_b[4];
#pragma unroll
    for (int g = 0; g < 4; g++) {
        int r = wn * 64 + g * 16 + lm;
        o_b[g] = (uint32_t)(r * 128) + (colb ^ ((r & 7) * 16));
    }

    float c[2][8][4];
#pragma unroll
    for (int mi = 0; mi < 2; mi++)
#pragma unroll
        for (int ni = 0; ni < 8; ni++)
#pragma unroll
            for (int j = 0; j < 4; j++) c[mi][ni][j] = 0.f;

    // ---- produce-side tile pointers ----
    const char* gAp;
    const char* gBp;
    int prod_id = blockIdx.x;
    {
        int mt, nt; tile_mn(prod_id, mt, nt);
        gAp = (const char*)g_X + (size_t)mt * BM * KDIM * 2;
        gBp = (const char*)g_W + (size_t)nt * BN * KDIM * 2;
    }

    auto fill_stage = [&](int kp, int s) {
        const uint32_t kb = (uint32_t)kp << 7;
#pragma unroll
        for (int p = 0; p < 4; p++) {
            cp16(sb + s * A_STG + soff[p], gAp + roff[p] + kb);
            cp16(sb + SMB + s * B_STG + soff[p], gBp + roff[p] + kb);
        }
    };

    if (tid == 0) {
#pragma unroll
        for (int s = 0; s < STAGES; s++) {
            mbar_init(fullb + s * 8, 256);
            mbar_init(emptyb + s * 8, 8);
        }
    }
    __syncthreads();

    const int G = gridDim.x;
    const int ntiles = 1 + (TOTAL_TILES - 1 - (int)blockIdx.x) / G;
    const int total = ntiles << 6;          // stages in this CTA's stream

    // prologue: stages g=0,1 (k=0,1 of first tile)
    fill_stage(0, 0); cp_arrive_noinc(fullb);
    fill_stage(1, 1); cp_arrive_noinc(fullb + 8);

    uint32_t a[2][2][4];
    uint32_t b[2][4][4];

    int cons_id = blockIdx.x;
    int cur = 0, phf = 0;
    int sslot = 2, sr = 0;

#pragma unroll 1
    for (int g = 0; g < total; g++) {
        const uint32_t sA = sb + cur * A_STG;
        const uint32_t sB = sb + SMB + cur * B_STG;

        wait_parity(fullb + cur * 8, (uint32_t)phf);

#pragma unroll
        for (int mi = 0; mi < 2; mi++) ldmx4(a[0][mi], sA + o_a[mi]);
#pragma unroll
        for (int gg = 0; gg < 4; gg++) ldmx4(b[0][gg], sB + o_b[gg]);

        // produce stage g+2 (crosses tile boundaries seamlessly)
        const int st = g + 2;
        if (st < total) {
            const int kp = st & 63;
            if (kp == 0) {                  // advance produce tile
                prod_id += G;
                int mt, nt; tile_mn(prod_id, mt, nt);
                gAp = (const char*)g_X + (size_t)mt * BM * KDIM * 2;
                gBp = (const char*)g_W + (size_t)nt * BN * KDIM * 2;
            }
            if (st >= STAGES) wait_parity(emptyb + sslot * 8, (uint32_t)((sr - 1) & 1));
            fill_stage(kp, sslot);
            cp_arrive_noinc(fullb + sslot * 8);
        }

#pragma unroll
        for (int ks = 0; ks < 4; ks++) {
            const int cb = ks & 1, nb = cb ^ 1;
            if (ks < 3) {
                const uint32_t ksc = (uint32_t)((ks + 1) << 5);
#pragma unroll
                for (int mi = 0; mi < 2; mi++) ldmx4(a[nb][mi], sA + (o_a[mi] ^ ksc));
#pragma unroll
                for (int gg = 0; gg < 4; gg++) ldmx4(b[nb][gg], sB + (o_b[gg] ^ ksc));
            }
#pragma unroll
            for (int mi = 0; mi < 2; mi++)
#pragma unroll
                for (int gg = 0; gg < 4; gg++) {
                    mma16816(c[mi][2 * gg + 0], a[cb][mi], b[cb][gg][0], b[cb][gg][2]);
                    mma16816(c[mi][2 * gg + 1], a[cb][mi], b[cb][gg][1], b[cb][gg][3]);
                }
        }

        if (lane == 0) mbar_arrive(emptyb + cur * 8);

        // tile finished -> epilogue under the in-flight next-tile loads
        if ((g & 63) == 63) {
            int mt, nt; tile_mn(cons_id, mt, nt);
            const int q = lane & 3, quad = lane >> 2;
            const int m_base = mt * BM + wm * 32;
            const int n_base = nt * BN + wn * 64;
#pragma unroll
            for (int ni = 0; ni < 8; ni++) {
                const int col = n_base + ni * 8 + q * 2;
                const float b0 = __ldg(bias + col), b1 = __ldg(bias + col + 1);
#pragma unroll
                for (int mi = 0; mi < 2; mi++) {
                    const int r0 = m_base + mi * 16 + quad;
                    float2 v0 = make_float2(c[mi][ni][0] + b0, c[mi][ni][1] + b1);
                    float2 v1 = make_float2(c[mi][ni][2] + b0, c[mi][ni][3] + b1);
                    *(float2*)(out + (size_t)r0 * NDIM + col) = v0;
                    *(float2*)(out + (size_t)(r0 + 8) * NDIM + col) = v1;
                    c[mi][ni][0] = 0.f; c[mi][ni][1] = 0.f;
                    c[mi][ni][2] = 0.f; c[mi][ni][3] = 0.f;
                }
            }
            cons_id += G;
        }

        if (++cur == STAGES) { cur = 0; phf ^= 1; }
        if (++sslot == STAGES) { sslot = 0; sr++; }
    }
}

// ---------------- launch ----------------
extern "C" void kernel_launch(void* const* d_in, const int* in_sizes, int n_in,
                              void* d_out, int out_size) {
    const float* x     = (const float*)d_in[0];
    const int*   qw    = (const int*)d_in[1];
    const float* scale = (const float*)d_in[2];
    const float* bias  = (const float*)d_in[3];
    float* out = (float*)d_out;

    int dev = 0, nsm = 148;
    cudaGetDevice(&dev);
    cudaDeviceGetAttribute(&nsm, cudaDevAttrMultiProcessorCount, dev);
    const int grid = 2 * nsm;               // all CTAs resident, never oversubscribed

    const int n4x = TOKENS * KDIM / 4;
    const int n4w = NDIM * KDIM / 4;

    k_convert_x<<<(n4x / 2 + 255) / 256, 256>>>((const float4*)x);
    k_dequant_w<<<(n4w / 2 + 255) / 256, 256>>>((const int4*)qw, scale);
    k_nop<<<1, 32>>>();
    cudaFuncSetAttribute(k_gemm, cudaFuncAttributeMaxDynamicSharedMemorySize, SMEM_TOTAL);
    k_gemm<<<grid, 256, SMEM_TOTAL>>>(bias, out);
    k_nop<<<1, 32>>>();
    k_nop<<<1, 32>>>();
}

// round 15
// speedup vs baseline: 1.0620x; 1.0620x over previous
#include <cuda_runtime.h>
#include <cuda_fp16.h>
#include <cstdint>

// ---------------- problem constants ----------------
#define TOKENS 8192
#define KDIM   4096
#define NDIM   11008

#define BM 128
#define BN 128
#define KT (KDIM/64)           // 64 k-tiles of 64 halves (128B rows)
#define MT (TOKENS/BM)         // 64
#define NT (NDIM/BN)           // 86
#define STAGES 3
#define A_STG (BM*64*2)        // 16384 B
#define B_STG (BN*64*2)        // 16384 B
#define SMB   (STAGES*A_STG)
#define SM_DATA (STAGES*(A_STG+B_STG))      // 98304 B
#define SM_MBAR SM_DATA
#define SMEM_TOTAL (SM_DATA + 64)

// fused prep partition: X blocks then W blocks (2 vectors of 16B per thread)
#define XBLK ((TOKENS*KDIM/4) / 512)        // 16384
#define WBLK ((NDIM*KDIM/4)   / 512)        // 22016

__device__ __half g_X[(size_t)TOKENS * KDIM];
__device__ __half g_W[(size_t)NDIM   * KDIM];

// ---------------- helpers ----------------
__device__ __forceinline__ uint32_t smem_u32(const void* p) {
    uint32_t a;
    asm("{ .reg .u64 t; cvta.to.shared.u64 t, %1; cvt.u32.u64 %0, t; }" : "=r"(a) : "l"(p));
    return a;
}
__device__ __forceinline__ void cp16(uint32_t dst, const void* src) {
    asm volatile("cp.async.cg.shared.global [%0], [%1], 16;" :: "r"(dst), "l"(src));
}
__device__ __forceinline__ void cp_arrive_noinc(uint32_t mbar) {
    asm volatile("cp.async.mbarrier.arrive.noinc.shared::cta.b64 [%0];" :: "r"(mbar) : "memory");
}
__device__ __forceinline__ void mbar_init(uint32_t mbar, uint32_t cnt) {
    asm volatile("mbarrier.init.shared.b64 [%0], %1;" :: "r"(mbar), "r"(cnt) : "memory");
}
__device__ __forceinline__ void mbar_arrive(uint32_t mbar) {
    asm volatile("mbarrier.arrive.shared.b64 _, [%0];" :: "r"(mbar) : "memory");
}
__device__ __forceinline__ void wait_parity(uint32_t mbar, uint32_t ph) {
    asm volatile(
        "{\n\t.reg .pred P;\n\t"
        "LAB1_%=:\n\t"
        "mbarrier.try_wait.parity.acquire.cta.shared::cta.b64 P, [%0], %1, 0x989680;\n\t"
        "@P bra.uni LAB2_%=;\n\t"
        "bra.uni LAB1_%=;\n\t"
        "LAB2_%=:\n\t}"
        :: "r"(mbar), "r"(ph) : "memory");
}
__device__ __forceinline__ void ldmx4(uint32_t* r, uint32_t addr) {
    asm volatile("ldmatrix.sync.aligned.m8n8.x4.shared.b16 {%0,%1,%2,%3}, [%4];"
                 : "=r"(r[0]), "=r"(r[1]), "=r"(r[2]), "=r"(r[3]) : "r"(addr));
}
__device__ __forceinline__ void mma16816(float* c, const uint32_t* a, uint32_t b0, uint32_t b1) {
    asm volatile(
        "mma.sync.aligned.m16n8k16.row.col.f32.f16.f16.f32 "
        "{%0,%1,%2,%3}, {%4,%5,%6,%7}, {%8,%9}, {%0,%1,%2,%3};"
        : "+f"(c[0]), "+f"(c[1]), "+f"(c[2]), "+f"(c[3])
        : "r"(a[0]), "r"(a[1]), "r"(a[2]), "r"(a[3]), "r"(b0), "r"(b1));
}
__device__ __forceinline__ uint32_t pack_h2(float a, float b) {
    __half2 h = __floats2half2_rn(a, b);
    return *reinterpret_cast<uint32_t*>(&h);
}

// ---------------- fused prep: one launch converts X and dequantizes W ----------------
__global__ void __launch_bounds__(256) k_prep(const float4* __restrict__ x,
                                              const int4* __restrict__ qw,
                                              const float* __restrict__ scale) {
    int b = blockIdx.x;
    if (b < XBLK) {
        int i = (b * 256 + threadIdx.x) * 2;
        float4 v0 = x[i], v1 = x[i + 1];
        ((uint2*)g_X)[i]     = make_uint2(pack_h2(v0.x, v0.y), pack_h2(v0.z, v0.w));
        ((uint2*)g_X)[i + 1] = make_uint2(pack_h2(v1.x, v1.y), pack_h2(v1.z, v1.w));
    } else {
        int i = ((b - XBLK) * 256 + threadIdx.x) * 2;
        int4 q0 = qw[i], q1 = qw[i + 1];
        float s = scale[i >> 10];   // both vectors in same row (1024 int4/row, i even)
        ((uint2*)g_W)[i]     = make_uint2(pack_h2((float)(q0.x - 8) * s, (float)(q0.y - 8) * s),
                                          pack_h2((float)(q0.z - 8) * s, (float)(q0.w - 8) * s));
        ((uint2*)g_W)[i + 1] = make_uint2(pack_h2((float)(q1.x - 8) * s, (float)(q1.y - 8) * s),
                                          pack_h2((float)(q1.z - 8) * s, (float)(q1.w - 8) * s));
    }
}

// ---------------- GEMM: 128x128, 8 warps, 2 CTAs/SM, mbarrier pipeline, kt unrolled x3 ----------------
__global__ void __launch_bounds__(256, 2) k_gemm(const float* __restrict__ bias,
                                                 float* __restrict__ out) {
    extern __shared__ char smem[];
    const uint32_t sb = smem_u32(smem);
    const int tid = threadIdx.x;
    const int wid = tid >> 5, lane = tid & 31;

    const uint32_t fullb  = sb + SM_MBAR;        // full[s]  (count 256)
    const uint32_t emptyb = sb + SM_MBAR + 24;   // empty[s] (count 8)

    const int GM = 16;
    int bid = blockIdx.x;
    int grp = bid / (GM * NT);
    int rem = bid - grp * (GM * NT);
    int mt = grp * GM + (rem % GM);
    int nt = rem / GM;

    const char* gA = (const char*)g_X + (size_t)mt * BM * KDIM * 2;
    const char* gB = (const char*)g_W + (size_t)nt * BN * KDIM * 2;

    const int lrow = tid >> 3;
    const int lcol = (tid & 7) * 16;
    uint32_t soff[4];
    const char* pA[4];
    const char* pB[4];
#pragma unroll
    for (int p = 0; p < 4; p++) {
        int row = lrow + p * 32;
        soff[p] = (uint32_t)(row * 128 + (lcol ^ ((row & 7) * 16)));
        pA[p] = gA + (size_t)row * (KDIM * 2) + lcol;
        pB[p] = gB + (size_t)row * (KDIM * 2) + lcol;
    }

    const int wm = wid & 3, wn = wid >> 2;
    const int lm   = ((lane >> 3) & 1) * 8 + (lane & 7);
    const uint32_t colb = (lane >> 4) * 16;

    uint32_t o_a[2];
#pragma unroll
    for (int mi = 0; mi < 2; mi++) {
        int r = wm * 32 + mi * 16 + lm;
        o_a[mi] = (uint32_t)(r * 128) + (colb ^ ((r & 7) * 16));
    }
    uint32_t o_b[4];
#pragma unroll
    for (int g = 0; g < 4; g++) {
        int r = wn * 64 + g * 16 + lm;
        o_b[g] = (uint32_t)(r * 128) + (colb ^ ((r & 7) * 16));
    }

    float c[2][8][4];
#pragma unroll
    for (int mi = 0; mi < 2; mi++)
#pragma unroll
        for (int ni = 0; ni < 8; ni++)
#pragma unroll
            for (int j = 0; j < 4; j++) c[mi][ni][j] = 0.f;

    auto fill_stage = [&](int st, int s) {
        const uint32_t kb = (uint32_t)st << 7;
#pragma unroll
        for (int p = 0; p < 4; p++) {
            cp16(sb + s * A_STG + soff[p], pA[p] + kb);
            cp16(sb + SMB + s * B_STG + soff[p], pB[p] + kb);
        }
    };

    if (tid == 0) {
#pragma unroll
        for (int s = 0; s < STAGES; s++) {
            mbar_init(fullb + s * 8, 256);
            mbar_init(emptyb + s * 8, 8);
        }
    }
    __syncthreads();

#pragma unroll
    for (int s = 0; s < STAGES - 1; s++) { fill_stage(s, s); cp_arrive_noinc(fullb + s * 8); }

    uint32_t a[2][2][4];
    uint32_t b[2][4][4];

    auto k_iter = [&](int kt, int cur, int sslot, uint32_t phf, uint32_t phe, bool ewait) {
        const uint32_t sA = sb + cur * A_STG;
        const uint32_t sB = sb + SMB + cur * B_STG;

        wait_parity(fullb + cur * 8, phf);

#pragma unroll
        for (int mi = 0; mi < 2; mi++) ldmx4(a[0][mi], sA + o_a[mi]);
#pragma unroll
        for (int g = 0; g < 4; g++)    ldmx4(b[0][g], sB + o_b[g]);

        const int st = kt + 2;
        if (st < KT) {
            if (ewait) wait_parity(emptyb + sslot * 8, phe);
            fill_stage(st, sslot);
            cp_arrive_noinc(fullb + sslot * 8);
        }

#pragma unroll
        for (int ks = 0; ks < 4; ks++) {
            const int cb = ks & 1, nb = cb ^ 1;
            if (ks < 3) {
                const uint32_t ksc = (uint32_t)((ks + 1) << 5);
#pragma unroll
                for (int mi = 0; mi < 2; mi++) ldmx4(a[nb][mi], sA + (o_a[mi] ^ ksc));
#pragma unroll
                for (int g = 0; g < 4; g++)    ldmx4(b[nb][g], sB + (o_b[g] ^ ksc));
            }
#pragma unroll
            for (int mi = 0; mi < 2; mi++)
#pragma unroll
                for (int g = 0; g < 4; g++) {
                    mma16816(c[mi][2 * g + 0], a[cb][mi], b[cb][g][0], b[cb][g][2]);
                    mma16816(c[mi][2 * g + 1], a[cb][mi], b[cb][g][1], b[cb][g][3]);
                }
        }

        if (lane == 0) mbar_arrive(emptyb + cur * 8);
    };

    uint32_t pp = 0;
#pragma unroll 1
    for (int kt3 = 0; kt3 < 63; kt3 += 3) {
        k_iter(kt3 + 0, 0, 2, pp, pp ^ 1, kt3 > 0);
        k_iter(kt3 + 1, 1, 0, pp, pp, true);
        k_iter(kt3 + 2, 2, 1, pp, pp, true);
        pp ^= 1;
    }
    // tail kt=63: cur=0, no produce
    {
        const uint32_t sA = sb;
        const uint32_t sB = sb + SMB;
        wait_parity(fullb, pp);
#pragma unroll
        for (int mi = 0; mi < 2; mi++) ldmx4(a[0][mi], sA + o_a[mi]);
#pragma unroll
        for (int g = 0; g < 4; g++)    ldmx4(b[0][g], sB + o_b[g]);
#pragma unroll
        for (int ks = 0; ks < 4; ks++) {
            const int cb = ks & 1, nb = cb ^ 1;
            if (ks < 3) {
                const uint32_t ksc = (uint32_t)((ks + 1) << 5);
#pragma unroll
                for (int mi = 0; mi < 2; mi++) ldmx4(a[nb][mi], sA + (o_a[mi] ^ ksc));
#pragma unroll
                for (int g = 0; g < 4; g++)    ldmx4(b[nb][g], sB + (o_b[g] ^ ksc));
            }
#pragma unroll
            for (int mi = 0; mi < 2; mi++)
#pragma unroll
                for (int g = 0; g < 4; g++) {
                    mma16816(c[mi][2 * g + 0], a[cb][mi], b[cb][g][0], b[cb][g][2]);
                    mma16816(c[mi][2 * g + 1], a[cb][mi], b[cb][g][1], b[cb][g][3]);
                }
        }
    }

    // ---- epilogue ----
    const int q = lane & 3, quad = lane >> 2;
    const int m_base = mt * BM + wm * 32;
    const int n_base = nt * BN + wn * 64;
#pragma unroll
    for (int ni = 0; ni < 8; ni++) {
        const int col = n_base + ni * 8 + q * 2;
        const float b0 = __ldg(bias + col), b1 = __ldg(bias + col + 1);
#pragma unroll
        for (int mi = 0; mi < 2; mi++) {
            const int r0 = m_base + mi * 16 + quad;
            float2 v0 = make_float2(c[mi][ni][0] + b0, c[mi][ni][1] + b1);
            float2 v1 = make_float2(c[mi][ni][2] + b0, c[mi][ni][3] + b1);
            *(float2*)(out + (size_t)r0 * NDIM + col) = v0;
            *(float2*)(out + (size_t)(r0 + 8) * NDIM + col) = v1;
        }
    }
}

// ---------------- launch ----------------
extern "C" void kernel_launch(void* const* d_in, const int* in_sizes, int n_in,
                              void* d_out, int out_size) {
    const float* x     = (const float*)d_in[0];
    const int*   qw    = (const int*)d_in[1];
    const float* scale = (const float*)d_in[2];
    const float* bias  = (const float*)d_in[3];
    float* out = (float*)d_out;

    k_prep<<<XBLK + WBLK, 256>>>((const float4*)x, (const int4*)qw, scale);
    cudaFuncSetAttribute(k_gemm, cudaFuncAttributeMaxDynamicSharedMemorySize, SMEM_TOTAL);
    k_gemm<<<MT * NT, 256, SMEM_TOTAL>>>(bias, out);
}